// round 14
// baseline (speedup 1.0000x reference)
#include <cuda_runtime.h>
#include <cuda_fp16.h>

typedef unsigned int u32; typedef unsigned short u16;

#define NN   800000
#define NF   100000
#define NR   2000
#define FEAT 86
#define H    128
#define NTILE_NODE 6250
#define NTILE_FRAG 782

#define A_B    32768            // A: 128 rows x 256 B (fp16)
#define S0_OFF 32768
#define S1_OFF 65536
#define DYN    98304            // A + 2 W slots -> 2 CTAs/SM

// ---------------- device scratch ----------------
__device__ __align__(16) u16   g_imgs[7 * 16384];   // fp16 weight images, swizzled, transposed
__device__ __align__(16) float g_root_emb[NR * H];
__device__ __align__(16) float g_frag_sum[(size_t)NF * H];
__device__ __align__(16) float g_cnt[NF];
__device__ u32 g_ctr[2];                            // work-stealing counters (node, frag)

// ---------------- helpers ----------------
__device__ __forceinline__ u32 smem_u32(const void* p) {
    u32 a; asm("{ .reg .u64 t; cvta.to.shared.u64 t, %1; cvt.u32.u64 %0, t; }" : "=r"(a) : "l"(p));
    return a;
}
__device__ __forceinline__ void cpa16(u32 dst, const void* src) {
    asm volatile("cp.async.ca.shared.global [%0], [%1], 16;" :: "r"(dst), "l"(src));
}
#define CPA_COMMIT() asm volatile("cp.async.commit_group;" ::: "memory")
#define CPA_WAIT0()  asm volatile("cp.async.wait_group 0;" ::: "memory")
#define CPA_WAIT1()  asm volatile("cp.async.wait_group 1;" ::: "memory")

#define LDSM4(d0, d1, d2, d3, a) \
    asm volatile("ldmatrix.sync.aligned.m8n8.x4.shared.b16 {%0,%1,%2,%3}, [%4];" \
                 : "=r"(d0), "=r"(d1), "=r"(d2), "=r"(d3) : "r"(a))

__device__ __forceinline__ u32 pack_h2(float v0, float v1) {
    __half2 h = __floats2half2_rn(v0, v1);
    return *(u32*)&h;
}
__device__ __forceinline__ void mma16816(float* c, u32 a0, u32 a1, u32 a2, u32 a3, u32 b0, u32 b1) {
    asm volatile("mma.sync.aligned.m16n8k16.row.col.f32.f16.f16.f32 "
                 "{%0,%1,%2,%3}, {%4,%5,%6,%7}, {%8,%9}, {%0,%1,%2,%3};"
                 : "+f"(c[0]), "+f"(c[1]), "+f"(c[2]), "+f"(c[3])
                 : "r"(a0), "r"(a1), "r"(a2), "r"(a3), "r"(b0), "r"(b1));
}

// swizzled byte offset, 256 B rows: chunk16 ^ (row & 7)
__device__ __forceinline__ int a_off(int r, int c) {      // c = u16 col 0..127
    return r * 256 + (((c >> 3) ^ (r & 7)) << 4) + (c & 7) * 2;
}
// pool: fp32, 512 B rows, 16B-chunk XOR swizzle
__device__ __forceinline__ int p_off(int r, int c) {      // c = f32 col 0..127
    return r * 512 + (((c >> 2) ^ (r & 7)) << 4) + (c & 3) * 4;
}

// ---------------- fully-unrolled GEMM pass: warp tile 64 x 32 ----------------
template<int NK>
__device__ __forceinline__ void mma_pass(float (&acc)[4][4][4],
                                         u32 aRow0, int aXor, int aSel,
                                         u32 wRow0, int wXor, int wSel) {
#pragma unroll
    for (int ks = 0; ks < NK; ks++) {
        u32 a[4][4];
#pragma unroll
        for (int mt = 0; mt < 4; mt++) {
            u32 ad = aRow0 + mt * 4096 + (u32)((((aSel + 2 * ks) ^ aXor) << 4));
            LDSM4(a[mt][0], a[mt][1], a[mt][2], a[mt][3], ad);
        }
        u32 b[2][4];
#pragma unroll
        for (int nb = 0; nb < 2; nb++) {
            u32 bd = wRow0 + nb * 4096 + (u32)((((2 * ks + wSel) ^ wXor) << 4));
            LDSM4(b[nb][0], b[nb][1], b[nb][2], b[nb][3], bd);
        }
#pragma unroll
        for (int mt = 0; mt < 4; mt++)
#pragma unroll
            for (int nb = 0; nb < 2; nb++) {
                mma16816(acc[mt][2 * nb + 0], a[mt][0], a[mt][1], a[mt][2], a[mt][3], b[nb][0], b[nb][1]);
                mma16816(acc[mt][2 * nb + 1], a[mt][0], a[mt][1], a[mt][2], a[mt][3], b[nb][2], b[nb][3]);
            }
    }
}
__device__ __forceinline__ void acc_zero(float (&acc)[4][4][4]) {
#pragma unroll
    for (int mt = 0; mt < 4; mt++)
#pragma unroll
        for (int nt = 0; nt < 4; nt++)
#pragma unroll
            for (int e = 0; e < 4; e++) acc[mt][nt][e] = 0.f;
}

// epilogue: acc + bias (+onehot) (+relu) -> fp16 into 256B-row A
__device__ __forceinline__ void epi16(char* Ab, float (&acc)[4][4][4],
                                      const float* __restrict__ bias,
                                      const float* __restrict__ sOne, const int* __restrict__ sBk,
                                      bool relu, int mrow0, int ncol0, int lane) {
    int gr = lane >> 2, q2 = (lane & 3) * 2;
#pragma unroll
    for (int mt = 0; mt < 4; mt++) {
        int r0 = mrow0 + mt * 16 + gr, r1 = r0 + 8;
        const float* oA = sOne ? (sOne + sBk[r0] * 132) : (const float*)0;
        const float* oB = sOne ? (sOne + sBk[r1] * 132) : (const float*)0;
#pragma unroll
        for (int nt = 0; nt < 4; nt++) {
            int c = ncol0 + nt * 8 + q2;
            float v0 = acc[mt][nt][0] + bias[c], v1 = acc[mt][nt][1] + bias[c + 1];
            float w0 = acc[mt][nt][2] + bias[c], w1 = acc[mt][nt][3] + bias[c + 1];
            if (oA) { v0 += oA[c]; v1 += oA[c + 1]; }
            if (oB) { w0 += oB[c]; w1 += oB[c + 1]; }
            if (relu) { v0 = fmaxf(v0, 0.f); v1 = fmaxf(v1, 0.f); w0 = fmaxf(w0, 0.f); w1 = fmaxf(w1, 0.f); }
            *(u32*)(Ab + a_off(r0, c)) = pack_h2(v0, v1);
            *(u32*)(Ab + a_off(r1, c)) = pack_h2(w0, w1);
        }
    }
}

__device__ __forceinline__ void load_img(u32 slot, const u16* src, int tid) {
    const uint4* s = (const uint4*)src;
    for (int i = tid; i < 2048; i += 256) cpa16(slot + i * 16, s + i);
}

// ---------------- fused prep + root encoder + scratch zeroing + counter reset ----------------
#define PREP_IMG_B 448
#define PREP_ROOT_B (NR / 2)
#define PREP_ZERO_B 2048
__global__ void prep_root_kernel(const float* __restrict__ W_in, const float* __restrict__ Wg1,
                                 const float* __restrict__ Wg2, const float* __restrict__ Wm1,
                                 const float* __restrict__ Wm2, const float* __restrict__ Wout,
                                 const float* __restrict__ Wattn,
                                 const float* __restrict__ root_repr,
                                 const float* __restrict__ W_root,
                                 const float* __restrict__ b_root) {
    int tid = threadIdx.x;
    if (blockIdx.x < PREP_IMG_B) {
        int idx = blockIdx.x * 256 + tid;
        int img = idx >> 14, r = idx & 16383, n = r >> 7, k = r & 127;
        float w = 0.f;
        if (img == 0)      { w = (k < FEAT) ? W_in[k * H + n] : 0.f; }
        else if (img == 1) w = Wg1[k * H + n];
        else if (img == 2) w = Wg2[k * H + n];
        else if (img == 3) w = Wm1[k * H + n] + Wm1[(H + k) * H + n];
        else if (img == 4) w = Wm1[(2 * H + k) * H + n] - Wm1[(H + k) * H + n];
        else if (img == 5) w = Wm2[k * H + n];
        else               w = (n < 13) ? Wout[k * 13 + n] : ((n < 26) ? Wattn[k * 13 + (n - 13)] : 0.f);
        int off = n * 128 + (((k >> 3) ^ (n & 7)) << 3) + (k & 7);
        g_imgs[img * 16384 + off] = __half_as_ushort(__float2half_rn(w));
    } else if (blockIdx.x < PREP_IMG_B + PREP_ROOT_B) {
        __shared__ float sX[2][FEAT];
        int half = tid >> 7, n = tid & 127;
        int r = (blockIdx.x - PREP_IMG_B) * 2 + half;
        for (int k = n; k < FEAT; k += 128) sX[half][k] = root_repr[r * FEAT + k];
        __syncthreads();
        float s = b_root[n];
#pragma unroll 2
        for (int k = 0; k < FEAT; k++) s += sX[half][k] * W_root[k * H + n];
        g_root_emb[r * H + n] = fmaxf(s, 0.f);
    } else {
        int zb = blockIdx.x - PREP_IMG_B - PREP_ROOT_B;
        if (zb == 0 && tid < 2) g_ctr[tid] = 0;
        uint4 z = make_uint4(0, 0, 0, 0);
        uint4* fs = (uint4*)g_frag_sum;
        const int NFS = (int)(((size_t)NF * H) / 4);
        for (int i = zb * 256 + tid; i < NFS; i += PREP_ZERO_B * 256) fs[i] = z;
        uint4* ct = (uint4*)g_cnt;
        for (int i = zb * 256 + tid; i < NF / 4; i += PREP_ZERO_B * 256) ct[i] = z;
    }
}

// ---------------- node chain: persistent + work stealing ----------------
__global__ __launch_bounds__(256, 2) void node_chain_kernel(
    const float* __restrict__ node_h, const int* __restrict__ seg,
    const float* __restrict__ b_in, const float* __restrict__ b_g1,
    const float* __restrict__ b_g2) {
    extern __shared__ __align__(16) char Ab[];
    __shared__ float sB[3][128];
    __shared__ int sSeg[128];
    __shared__ int sTile;

    int tid = threadIdx.x, lane = tid & 31, w = tid >> 5;
    int mrow0 = (w >> 2) * 64, ncol0 = (w & 3) * 32;
    u32 smA = smem_u32(Ab);
    u32 S0 = smA + S0_OFF, S1 = smA + S1_OFF;

    load_img(S0, g_imgs, tid);           CPA_COMMIT();   // W0
    load_img(S1, g_imgs + 16384, tid);   CPA_COMMIT();   // W1 (resident forever)

    if (tid < 128) { sB[0][tid] = b_in[tid]; sB[1][tid] = b_g1[tid]; sB[2][tid] = b_g2[tid]; }
    if (tid == 0) sTile = (int)atomicAdd(&g_ctr[0], 1u);

    int rowA = mrow0 + (lane & 15);
    u32 aRow0 = smA + rowA * 256; int aXor = rowA & 7; int aSel = lane >> 4;
    int rowB = ncol0 + (lane & 7) + ((lane >> 4) << 3);
    u32 wOff = rowB * 256; int wXor = rowB & 7; int wSel = (lane >> 3) & 1;

    __syncthreads();
    int tile = sTile;

    while (tile < NTILE_NODE) {
        int tilebase = tile * 128;

        if (tid < 128) sSeg[tid] = seg[tilebase + tid];
        for (int i = tid; i < 128 * 5; i += 256) {
            int m = i / 5, k = 86 + (i - 5 * (i / 5)) * 2;
            *(u32*)(Ab + a_off(m, k)) = 0;
        }
        for (int idx = tid; idx < 128 * 43; idx += 256) {
            int m = idx / 43, k = (idx - m * 43) * 2;
            float2 v = *(const float2*)(node_h + (size_t)(tilebase + m) * FEAT + k);
            *(u32*)(Ab + a_off(m, k)) = pack_h2(v.x, v.y);
        }
        CPA_WAIT0(); __syncthreads();       // W0 ready (first tile also W1)

        float acc[4][4][4];

        // ---- L0 (K=96) ----
        acc_zero(acc);
        mma_pass<6>(acc, aRow0, aXor, aSel, S0 + wOff, wXor, wSel);
        __syncthreads();
        load_img(S0, g_imgs + 2 * 16384, tid); CPA_COMMIT();   // W2 -> S0
        epi16(Ab, acc, sB[0], (const float*)0, (const int*)0, false, mrow0, ncol0, lane);
        __syncthreads();

        // ---- L1 (W1 resident in S1) ----
        acc_zero(acc);
        mma_pass<8>(acc, aRow0, aXor, aSel, S1 + wOff, wXor, wSel);
        __syncthreads();
        epi16(Ab, acc, sB[1], (const float*)0, (const int*)0, true, mrow0, ncol0, lane);
        CPA_WAIT0(); __syncthreads();       // W2 ready

        // ---- L2 -> pool ----
        acc_zero(acc);
        mma_pass<8>(acc, aRow0, aXor, aSel, S0 + wOff, wXor, wSel);
        if (tid == 0) sTile = (int)atomicAdd(&g_ctr[0], 1u);   // early grab, hidden under MMA/epi
        __syncthreads();
        {
            int gr = lane >> 2, q2 = (lane & 3) * 2;
#pragma unroll
            for (int mt = 0; mt < 4; mt++) {
                int r0 = mrow0 + mt * 16 + gr, r1 = r0 + 8;
#pragma unroll
                for (int nt = 0; nt < 4; nt++) {
                    int c = ncol0 + nt * 8 + q2;
                    *(float2*)(Ab + p_off(r0, c)) =
                        make_float2(fmaxf(acc[mt][nt][0] + sB[2][c], 0.f),
                                    fmaxf(acc[mt][nt][1] + sB[2][c + 1], 0.f));
                    *(float2*)(Ab + p_off(r1, c)) =
                        make_float2(fmaxf(acc[mt][nt][2] + sB[2][c], 0.f),
                                    fmaxf(acc[mt][nt][3] + sB[2][c + 1], 0.f));
                }
            }
        }
        __syncthreads();

        // sorted-segment run-length pooling
        {
            int col = tid & 127, hh = tid >> 7;
            int r0 = hh * 64;
            float r = 0.f; int cur = sSeg[r0];
            for (int m = r0; m < r0 + 64; m++) {
                int s = sSeg[m];
                if (s != cur) { atomicAdd(&g_frag_sum[(size_t)cur * H + col], r); r = 0.f; cur = s; }
                r += *(const float*)(Ab + p_off(m, col));
            }
            atomicAdd(&g_frag_sum[(size_t)cur * H + col], r);
        }
        if (tid < 8) {
            int r0 = tid * 16;
            float c = 0.f; int cur = sSeg[r0];
            for (int m = r0; m < r0 + 16; m++) {
                int s = sSeg[m];
                if (s != cur) { atomicAdd(&g_cnt[cur], c); c = 0.f; cur = s; }
                c += 1.f;
            }
            atomicAdd(&g_cnt[cur], c);
        }
        __syncthreads();
        tile = sTile;
        if (tile < NTILE_NODE) { load_img(S0, g_imgs, tid); CPA_COMMIT(); }   // W0 reload
    }
}

// ---------------- fragment head: persistent + work stealing ----------------
__global__ __launch_bounds__(256, 2) void frag_mlp_kernel(
    const int* __restrict__ ind_maps, const int* __restrict__ broken,
    const float* __restrict__ W_m1, const float* __restrict__ b_m1,
    const float* __restrict__ b_m2, const float* __restrict__ b_out,
    const float* __restrict__ b_attn, float* __restrict__ out) {
    extern __shared__ __align__(16) char Ab[];
    __shared__ int sInd[128]; __shared__ float sInv[128]; __shared__ int sBk[128];
    __shared__ float sB1[128], sB2[128], sBo[26];
    __shared__ float sOne[13 * 132];
    __shared__ int sTile;

    int tid = threadIdx.x, lane = tid & 31, w = tid >> 5;
    int mrow0 = (w >> 2) * 64, ncol0 = (w & 3) * 32;
    u32 smA = smem_u32(Ab);
    u32 S0 = smA + S0_OFF, S1 = smA + S1_OFF;

    load_img(S0, g_imgs + 3 * 16384, tid); CPA_COMMIT();   // Wa
    load_img(S1, g_imgs + 4 * 16384, tid); CPA_COMMIT();   // Wb

    if (tid < 128) { sB1[tid] = b_m1[tid]; sB2[tid] = b_m2[tid]; }
    if (tid < 26) sBo[tid] = (tid < 13) ? b_out[tid] : b_attn[tid - 13];
    for (int i = tid; i < 13 * 128; i += 256) {
        int rr = i >> 7, c = i & 127;
        sOne[rr * 132 + c] = W_m1[(size_t)(384 + rr) * H + c];
    }
    if (tid == 0) sTile = (int)atomicAdd(&g_ctr[1], 1u);

    int rowA = mrow0 + (lane & 15);
    u32 aRow0 = smA + rowA * 256; int aXor = rowA & 7; int aSel = lane >> 4;
    int rowB = ncol0 + (lane & 7) + ((lane >> 4) << 3);
    u32 wOff = rowB * 256; int wXor = rowB & 7; int wSel = (lane >> 3) & 1;

    __syncthreads();
    int tile = sTile;

    while (tile < NTILE_FRAG) {
        int base = tile * 128;

        if (tid < 128) {
            int f = base + tid;
            sInd[tid] = (f < NF) ? ind_maps[f] : 0;
            sInv[tid] = (f < NF) ? 1.f / fmaxf(g_cnt[f], 1.f) : 0.f;
            int b = (f < NF) ? broken[f] : 0;
            sBk[tid] = min(max(b, 0), 12);
        }
        __syncthreads();

        // stage ext-root rows (float4)
        for (int idx = tid; idx < 128 * 32; idx += 256) {
            int m = idx >> 5, k = (idx & 31) * 4;
            float4 v = *(const float4*)(g_root_emb + (size_t)sInd[m] * H + k);
            *(uint2*)(Ab + a_off(m, k)) = make_uint2(pack_h2(v.x, v.y), pack_h2(v.z, v.w));
        }
        CPA_WAIT0(); __syncthreads();       // Wa, Wb ready

        float acc[4][4][4];
        acc_zero(acc);

        // ---- L1a: ext @ Wa ----
        mma_pass<8>(acc, aRow0, aXor, aSel, S0 + wOff, wXor, wSel);
        __syncthreads();
        load_img(S0, g_imgs + 5 * 16384, tid); CPA_COMMIT();   // Wm2 -> S0
        for (int idx = tid; idx < 128 * 32; idx += 256) {      // restage A = mean rows (float4)
            int m = idx >> 5, k = (idx & 31) * 4;
            int f = base + m;
            float4 v = make_float4(0.f, 0.f, 0.f, 0.f);
            float iv = sInv[m];
            if (f < NF) {
                v = *(const float4*)(g_frag_sum + (size_t)f * H + k);
                v.x *= iv; v.y *= iv; v.z *= iv; v.w *= iv;
            }
            *(uint2*)(Ab + a_off(m, k)) = make_uint2(pack_h2(v.x, v.y), pack_h2(v.z, v.w));
        }
        __syncthreads();

        // ---- L1b: += mean @ Wb ----
        mma_pass<8>(acc, aRow0, aXor, aSel, S1 + wOff, wXor, wSel);
        __syncthreads();
        load_img(S1, g_imgs + 6 * 16384, tid); CPA_COMMIT();   // Wout -> S1
        epi16(Ab, acc, sB1, sOne, sBk, true, mrow0, ncol0, lane);
        CPA_WAIT1(); __syncthreads();       // Wm2 ready (FIFO)

        // ---- L2 ----
        acc_zero(acc);
        mma_pass<8>(acc, aRow0, aXor, aSel, S0 + wOff, wXor, wSel);
        __syncthreads();
        epi16(Ab, acc, sB2, (const float*)0, (const int*)0, true, mrow0, ncol0, lane);
        CPA_WAIT0(); __syncthreads();       // Wout ready

        // ---- out layer: cols 0..25 ----
        if (tid == 0) sTile = (int)atomicAdd(&g_ctr[1], 1u);   // early grab
        if (ncol0 == 0) {
            acc_zero(acc);
            mma_pass<8>(acc, aRow0, aXor, aSel, S1 + wOff, wXor, wSel);
            int gr = lane >> 2, q2 = (lane & 3) * 2;
#pragma unroll
            for (int mt = 0; mt < 4; mt++) {
                int r0 = mrow0 + mt * 16 + gr, r1 = r0 + 8;
                int fA = base + r0, fB = base + r1;
#pragma unroll
                for (int nt = 0; nt < 4; nt++) {
#pragma unroll
                    for (int e = 0; e < 2; e++) {
                        int c = nt * 8 + q2 + e;
                        if (c >= 26) continue;
                        if (fA < NF) {
                            float v = acc[mt][nt][e] + sBo[c];
                            if (c < 13) out[(size_t)fA * 13 + c] = 1.f / (1.f + __expf(-v));
                            else        out[(size_t)NF * 13 + (size_t)fA * 13 + (c - 13)] = v;
                        }
                        if (fB < NF) {
                            float v = acc[mt][nt][2 + e] + sBo[c];
                            if (c < 13) out[(size_t)fB * 13 + c] = 1.f / (1.f + __expf(-v));
                            else        out[(size_t)NF * 13 + (size_t)fB * 13 + (c - 13)] = v;
                        }
                    }
                }
            }
        }
        __syncthreads();
        tile = sTile;
        if (tile < NTILE_FRAG) {
            load_img(S0, g_imgs + 3 * 16384, tid); CPA_COMMIT();   // Wa
            load_img(S1, g_imgs + 4 * 16384, tid); CPA_COMMIT();   // Wb
        }
    }
}

// ---------------- launcher ----------------
extern "C" void kernel_launch(void* const* d_in, const int* in_sizes, int n_in,
                              void* d_out, int out_size) {
    const float* node_h    = (const float*)d_in[0];
    const int*   seg       = (const int*)d_in[1];
    const float* root_repr = (const float*)d_in[2];
    const int*   ind_maps  = (const int*)d_in[3];
    const int*   broken    = (const int*)d_in[4];
    const float* W_root = (const float*)d_in[5];  const float* b_root = (const float*)d_in[6];
    const float* W_in   = (const float*)d_in[7];  const float* b_in   = (const float*)d_in[8];
    const float* W_g1   = (const float*)d_in[9];  const float* b_g1   = (const float*)d_in[10];
    const float* W_g2   = (const float*)d_in[11]; const float* b_g2   = (const float*)d_in[12];
    const float* W_m1   = (const float*)d_in[13]; const float* b_m1   = (const float*)d_in[14];
    const float* W_m2   = (const float*)d_in[15]; const float* b_m2   = (const float*)d_in[16];
    const float* W_out  = (const float*)d_in[17]; const float* b_out  = (const float*)d_in[18];
    const float* W_attn = (const float*)d_in[19]; const float* b_attn = (const float*)d_in[20];
    float* out = (float*)d_out;

    int nsm = 148;
    cudaDeviceGetAttribute(&nsm, cudaDevAttrMultiProcessorCount, 0);
    int grid = 2 * nsm;

    cudaFuncSetAttribute(node_chain_kernel, cudaFuncAttributeMaxDynamicSharedMemorySize, DYN);
    cudaFuncSetAttribute(frag_mlp_kernel,   cudaFuncAttributeMaxDynamicSharedMemorySize, DYN);

    prep_root_kernel<<<PREP_IMG_B + PREP_ROOT_B + PREP_ZERO_B, 256>>>(
        W_in, W_g1, W_g2, W_m1, W_m2, W_out, W_attn, root_repr, W_root, b_root);
    node_chain_kernel<<<grid, 256, DYN>>>(node_h, seg, b_in, b_g1, b_g2);
    frag_mlp_kernel<<<grid, 256, DYN>>>(ind_maps, broken, W_m1, b_m1,
                                        b_m2, b_out, b_attn, out);
}